// round 10
// baseline (speedup 1.0000x reference)
#include <cuda_runtime.h>
#include <cuda_fp16.h>
#include <cstdint>
#include <cstddef>

#define N_NODES 100000
#define N_EDGES 3200000
#define IN_DIM  256
#define HID     128
#define OUT_DIM 2
#define BN_EPS  1e-5f

#define SC_BLOCKS 100
#define SC_THREADS 256
#define SC_PER 4   // 100*256*4 = 102400 >= N_NODES

#define GBM 128
#define GBK 32
#define A_S 36
#define B_S 132
#define NBLK_GEMM ((N_NODES + GBM - 1) / GBM)          // 782
#define G1 521                                          // gemm tiles in fuse1
#define G2 (NBLK_GEMM - G1)                             // 261 tiles in fuse2
#define NBLK_EDGE ((N_EDGES / 8 + 255) / 256)          // 1563 (deg & fill)
#define FUSE1_BLOCKS (G1 * 4)                           // 2084 = 521 gemm + 1563 edge
#define FUSE2_BLOCKS (G2 * 7)                           // 1827 = 261 gemm + <=1566 edge

// ---------------- scratch (static device globals; no runtime alloc) --------
__device__ __align__(16) float  g_dinv[N_NODES];
__device__ __align__(16) __half g_h1s[(size_t)N_NODES * HID];   // fp16 h1 (unscaled)
__device__ __align__(16) __half g_hpre[(size_t)N_NODES * HID];  // fp16 pre-BN h
__device__ __align__(16) float  g_h2s[N_NODES * OUT_DIM];
__device__ __align__(16) float  g_W1s[IN_DIM * HID];            // tf32-rounded W1*sig(fi)
__device__ __align__(16) float  g_sums[HID];
__device__ __align__(16) float  g_sumsq[HID];
// CSR by destination
__device__ __align__(16) int    g_cnt[N_NODES];
__device__ __align__(16) int    g_off[N_NODES + 1];
__device__ __align__(16) int    g_cursor[N_NODES];
__device__ __align__(16) int    g_csr_row[N_EDGES];
// scan scratch
__device__ __align__(16) int    g_tpref[SC_BLOCKS * SC_THREADS];
__device__ __align__(16) int    g_bpart[SC_BLOCKS];

// ---------------- helpers ---------------------------------------------------
__device__ __forceinline__ float to_tf32(float x) {
    uint32_t u;
    asm("cvt.rna.tf32.f32 %0, %1;" : "=r"(u) : "f"(x));
    return __uint_as_float(u);
}

__device__ __forceinline__ void mma_tf32(float* c,
                                         uint32_t a0, uint32_t a1, uint32_t a2, uint32_t a3,
                                         uint32_t b0, uint32_t b1) {
    asm volatile(
        "mma.sync.aligned.m16n8k8.row.col.f32.tf32.tf32.f32 "
        "{%0,%1,%2,%3}, {%4,%5,%6,%7}, {%8,%9}, {%0,%1,%2,%3};"
        : "+f"(c[0]), "+f"(c[1]), "+f"(c[2]), "+f"(c[3])
        : "r"(a0), "r"(a1), "r"(a2), "r"(a3), "r"(b0), "r"(b1));
}

// ---------------- GEMM tile worker (one 128x128 output tile) ----------------
__device__ __forceinline__ void gemm_tile(const float* __restrict__ x, int tile) {
    __shared__ float As[GBM * A_S];
    __shared__ float Bs[GBK * B_S];
    const int m0   = tile * GBM;
    const int tid  = threadIdx.x;
    const int lane = tid & 31;
    const int wid  = tid >> 5;
    const int wm   = wid >> 2;
    const int wn   = wid & 3;
    const int grp  = lane >> 2;
    const int tg   = lane & 3;

    float acc[4][4][4];
    #pragma unroll
    for (int im = 0; im < 4; ++im)
        #pragma unroll
        for (int in = 0; in < 4; ++in)
            #pragma unroll
            for (int q = 0; q < 4; ++q) acc[im][in][q] = 0.f;

    float4 ra[4];

    auto loadA = [&](int k0) {
        #pragma unroll
        for (int p = 0; p < 4; ++p) {
            int slot = tid + p * 256;
            int r = slot >> 3;
            int q = slot & 7;
            int gm = m0 + r;
            ra[p] = make_float4(0.f, 0.f, 0.f, 0.f);
            if (gm < N_NODES)
                ra[p] = *(const float4*)(x + (size_t)gm * IN_DIM + k0 + q * 4);
        }
    };
    auto storeA = [&]() {
        #pragma unroll
        for (int p = 0; p < 4; ++p) {
            int slot = tid + p * 256;
            int r = slot >> 3;
            int q = slot & 7;
            float* dst = As + r * A_S + q * 4;
            dst[0] = to_tf32(ra[p].x);
            dst[1] = to_tf32(ra[p].y);
            dst[2] = to_tf32(ra[p].z);
            dst[3] = to_tf32(ra[p].w);
        }
    };
    auto loadstoreB = [&](int k0) {
        #pragma unroll
        for (int p = 0; p < 4; ++p) {
            int slot = tid + p * 256;
            int r = slot >> 5;
            int c = slot & 31;
            float4 v = *(const float4*)(g_W1s + (size_t)(k0 + r) * HID + c * 4);
            *(float4*)(Bs + r * B_S + c * 4) = v;   // already tf32-rounded
        }
    };

    const int NT = IN_DIM / GBK;   // 8
    loadA(0);
    for (int t = 0; t < NT; ++t) {
        storeA();
        loadstoreB(t * GBK);
        __syncthreads();
        if (t + 1 < NT) loadA((t + 1) * GBK);

        #pragma unroll
        for (int ks = 0; ks < GBK; ks += 8) {
            uint32_t a[4][4], b[4][2];
            #pragma unroll
            for (int im = 0; im < 4; ++im) {
                int mb = wm * 64 + im * 16;
                const float* pa = As + (mb + grp) * A_S + ks + tg;
                a[im][0] = __float_as_uint(pa[0]);
                a[im][1] = __float_as_uint(pa[8 * A_S]);
                a[im][2] = __float_as_uint(pa[4]);
                a[im][3] = __float_as_uint(pa[8 * A_S + 4]);
            }
            #pragma unroll
            for (int in = 0; in < 4; ++in) {
                int nb = wn * 32 + in * 8 + grp;
                const float* pb = Bs + (ks + tg) * B_S + nb;
                b[in][0] = __float_as_uint(pb[0]);
                b[in][1] = __float_as_uint(pb[4 * B_S]);
            }
            #pragma unroll
            for (int im = 0; im < 4; ++im)
                #pragma unroll
                for (int in = 0; in < 4; ++in)
                    mma_tf32(acc[im][in], a[im][0], a[im][1], a[im][2], a[im][3],
                             b[in][0], b[in][1]);
        }
        __syncthreads();
    }

    #pragma unroll
    for (int im = 0; im < 4; ++im) {
        int r0 = m0 + wm * 64 + im * 16 + grp;
        int r1 = r0 + 8;
        #pragma unroll
        for (int in = 0; in < 4; ++in) {
            int col = wn * 32 + in * 8 + tg * 2;
            if (r0 < N_NODES) {
                __half2 h = __floats2half2_rn(acc[im][in][0], acc[im][in][1]);
                *(__half2*)(g_h1s + (size_t)r0 * HID + col) = h;
            }
            if (r1 < N_NODES) {
                __half2 h = __floats2half2_rn(acc[im][in][2], acc[im][in][3]);
                *(__half2*)(g_h1s + (size_t)r1 * HID + col) = h;
            }
        }
    }
}

// ---------------- edge workers ----------------------------------------------
__device__ __forceinline__ void deg_block(const int* __restrict__ ei, int eb) {
    int t = eb * 256 + threadIdx.x;
    int e8 = t * 8;
    if (e8 >= N_EDGES) return;
    int4 c0 = *(const int4*)(ei + N_EDGES + e8);
    int4 c1 = *(const int4*)(ei + N_EDGES + e8 + 4);
    atomicAdd(&g_cnt[c0.x], 1);
    atomicAdd(&g_cnt[c0.y], 1);
    atomicAdd(&g_cnt[c0.z], 1);
    atomicAdd(&g_cnt[c0.w], 1);
    atomicAdd(&g_cnt[c1.x], 1);
    atomicAdd(&g_cnt[c1.y], 1);
    atomicAdd(&g_cnt[c1.z], 1);
    atomicAdd(&g_cnt[c1.w], 1);
}

__device__ __forceinline__ void fill_block(const int* __restrict__ ei, int eb) {
    int t = eb * 256 + threadIdx.x;
    int e8 = t * 8;
    if (e8 >= N_EDGES) return;
    int4 r0 = *(const int4*)(ei + e8);
    int4 r1 = *(const int4*)(ei + e8 + 4);
    int4 c0 = *(const int4*)(ei + N_EDGES + e8);
    int4 c1 = *(const int4*)(ei + N_EDGES + e8 + 4);
    int p0 = atomicAdd(&g_cursor[c0.x], 1);
    int p1 = atomicAdd(&g_cursor[c0.y], 1);
    int p2 = atomicAdd(&g_cursor[c0.z], 1);
    int p3 = atomicAdd(&g_cursor[c0.w], 1);
    int p4 = atomicAdd(&g_cursor[c1.x], 1);
    int p5 = atomicAdd(&g_cursor[c1.y], 1);
    int p6 = atomicAdd(&g_cursor[c1.z], 1);
    int p7 = atomicAdd(&g_cursor[c1.w], 1);
    g_csr_row[p0] = r0.x;
    g_csr_row[p1] = r0.y;
    g_csr_row[p2] = r0.z;
    g_csr_row[p3] = r0.w;
    g_csr_row[p4] = r1.x;
    g_csr_row[p5] = r1.y;
    g_csr_row[p6] = r1.z;
    g_csr_row[p7] = r1.w;
}

// ---------------- K0: prep (fold sigmoid into W1 -> tf32, zero counters) ----
__global__ void k_prep(const float* __restrict__ W1, const float* __restrict__ fi) {
    int i = blockIdx.x * blockDim.x + threadIdx.x;
    if (i < IN_DIM * HID) {
        int k = i / HID;
        float s = 1.0f / (1.0f + __expf(-fi[k]));
        g_W1s[i] = to_tf32(W1[i] * s);
    }
    if (i < N_NODES) g_cnt[i] = 0;
    if (i < HID) { g_sums[i] = 0.0f; g_sumsq[i] = 0.0f; }
}

// ---------------- K1: INTERLEAVED  GEMM tiles [0,G1) + degree histogram -----
// bid%4==0 -> gemm tile bid/4 ; else edge block (bid/4)*3 + bid%4 - 1
__global__ __launch_bounds__(256, 2) void k_fuse1(const float* __restrict__ x,
                                                  const int* __restrict__ ei) {
    int g = blockIdx.x >> 2;
    int r = blockIdx.x & 3;
    if (r == 0) {
        gemm_tile(x, g);
    } else {
        int eb = g * 3 + (r - 1);
        if (eb < NBLK_EDGE) deg_block(ei, eb);
    }
}

// ---------------- K2a: per-thread chunk sums + block scan -------------------
__global__ __launch_bounds__(SC_THREADS) void k_scan1() {
    __shared__ int sm[SC_THREADS];
    int t = threadIdx.x, b = blockIdx.x;
    int base = (b * SC_THREADS + t) * SC_PER;
    int s = 0;
    #pragma unroll
    for (int q = 0; q < SC_PER; ++q) {
        int i = base + q;
        if (i < N_NODES) s += g_cnt[i];
    }
    sm[t] = s;
    __syncthreads();
    for (int off = 1; off < SC_THREADS; off <<= 1) {
        int v = (t >= off) ? sm[t - off] : 0;
        __syncthreads();
        sm[t] += v;
        __syncthreads();
    }
    g_tpref[b * SC_THREADS + t] = sm[t] - s;   // exclusive
    if (t == SC_THREADS - 1) g_bpart[b] = sm[t];
}

// ---------------- K2c: scan partials in-block + finalize ---------------------
__global__ __launch_bounds__(SC_THREADS) void k_scan3() {
    __shared__ int bp[SC_BLOCKS];
    int t = threadIdx.x, b = blockIdx.x;
    if (t < SC_BLOCKS) bp[t] = g_bpart[t];
    __syncthreads();
    if (t == 0) {
        int run = 0;
        #pragma unroll 4
        for (int i = 0; i < SC_BLOCKS; ++i) { int c = bp[i]; bp[i] = run; run += c; }
    }
    __syncthreads();
    int tid_g = b * SC_THREADS + t;
    int base = tid_g * SC_PER;
    int run = bp[b] + g_tpref[tid_g];
    #pragma unroll
    for (int q = 0; q < SC_PER; ++q) {
        int i = base + q;
        if (i < N_NODES) {
            int c = g_cnt[i];
            g_off[i] = run;
            g_cursor[i] = run;
            g_dinv[i] = rsqrtf((float)(c + 1));
            run += c;
            if (i == N_NODES - 1) g_off[N_NODES] = run;
        }
    }
}

// ---------------- K3: INTERLEAVED  GEMM tiles [G1,782) + CSR fill ------------
// bid%7==0 -> gemm tile G1 + bid/7 ; else edge block (bid/7)*6 + bid%7 - 1
__global__ __launch_bounds__(256, 2) void k_fuse2(const float* __restrict__ x,
                                                  const int* __restrict__ ei) {
    int g = blockIdx.x / 7;
    int r = blockIdx.x % 7;
    if (r == 0) {
        gemm_tile(x, G1 + g);
    } else {
        int eb = g * 6 + (r - 1);
        if (eb < NBLK_EDGE) fill_block(ei, eb);
    }
}

// ---------------- K5: layer-1 aggregation (dinv at gather) + BN stats -------
__global__ __launch_bounds__(256) void k_agg1(const float* __restrict__ b1) {
    __shared__ float s_sum[HID];
    __shared__ float s_sq[HID];
    const int tid  = threadIdx.x;
    const int lane = tid & 31;
    const int warp = tid >> 5;
    if (tid < HID) { s_sum[tid] = 0.f; s_sq[tid] = 0.f; }
    __syncthreads();

    int n = blockIdx.x * 8 + warp;
    if (n < N_NODES) {
        int s = g_off[n], e = g_off[n + 1];
        float dn = g_dinv[n];
        float4 v;
        {
            uint2 u = ((const uint2*)(g_h1s + (size_t)n * HID))[lane];
            float2 fa = __half22float2(*(__half2*)&u.x);
            float2 fb = __half22float2(*(__half2*)&u.y);
            v = make_float4(dn * fa.x, dn * fa.y, dn * fb.x, dn * fb.y);
        }
        int i = s;
        for (; i + 4 <= e; i += 4) {
            int r0 = g_csr_row[i];
            int r1 = g_csr_row[i + 1];
            int r2 = g_csr_row[i + 2];
            int r3 = g_csr_row[i + 3];
            float d0 = g_dinv[r0], d1 = g_dinv[r1], d2 = g_dinv[r2], d3 = g_dinv[r3];
            uint2 u0 = ((const uint2*)(g_h1s + (size_t)r0 * HID))[lane];
            uint2 u1 = ((const uint2*)(g_h1s + (size_t)r1 * HID))[lane];
            uint2 u2 = ((const uint2*)(g_h1s + (size_t)r2 * HID))[lane];
            uint2 u3 = ((const uint2*)(g_h1s + (size_t)r3 * HID))[lane];
            float2 a0 = __half22float2(*(__half2*)&u0.x), b0 = __half22float2(*(__half2*)&u0.y);
            float2 a1 = __half22float2(*(__half2*)&u1.x), b1f = __half22float2(*(__half2*)&u1.y);
            float2 a2 = __half22float2(*(__half2*)&u2.x), b2f = __half22float2(*(__half2*)&u2.y);
            float2 a3 = __half22float2(*(__half2*)&u3.x), b3f = __half22float2(*(__half2*)&u3.y);
            v.x = fmaf(d0, a0.x, v.x); v.y = fmaf(d0, a0.y, v.y);
            v.z = fmaf(d0, b0.x, v.z); v.w = fmaf(d0, b0.y, v.w);
            v.x = fmaf(d1, a1.x, v.x); v.y = fmaf(d1, a1.y, v.y);
            v.z = fmaf(d1, b1f.x, v.z); v.w = fmaf(d1, b1f.y, v.w);
            v.x = fmaf(d2, a2.x, v.x); v.y = fmaf(d2, a2.y, v.y);
            v.z = fmaf(d2, b2f.x, v.z); v.w = fmaf(d2, b2f.y, v.w);
            v.x = fmaf(d3, a3.x, v.x); v.y = fmaf(d3, a3.y, v.y);
            v.z = fmaf(d3, b3f.x, v.z); v.w = fmaf(d3, b3f.y, v.w);
        }
        for (; i < e; ++i) {
            int r0 = g_csr_row[i];
            float d0 = g_dinv[r0];
            uint2 u0 = ((const uint2*)(g_h1s + (size_t)r0 * HID))[lane];
            float2 a0 = __half22float2(*(__half2*)&u0.x), b0 = __half22float2(*(__half2*)&u0.y);
            v.x = fmaf(d0, a0.x, v.x); v.y = fmaf(d0, a0.y, v.y);
            v.z = fmaf(d0, b0.x, v.z); v.w = fmaf(d0, b0.y, v.w);
        }

        float vv[4] = {v.x, v.y, v.z, v.w};
        float hh[4];
        #pragma unroll
        for (int q = 0; q < 4; ++q) {
            int j = lane * 4 + q;
            hh[q] = fmaf(dn, vv[q], __ldg(b1 + j));
            atomicAdd(&s_sum[j], hh[q]);
            atomicAdd(&s_sq[j], hh[q] * hh[q]);
        }
        uint2 o;
        *(__half2*)&o.x = __floats2half2_rn(hh[0], hh[1]);
        *(__half2*)&o.y = __floats2half2_rn(hh[2], hh[3]);
        ((uint2*)(g_hpre + (size_t)n * HID))[lane] = o;
    }
    __syncthreads();
    if (tid < HID) {
        atomicAdd(&g_sums[tid], s_sum[tid]);
        atomicAdd(&g_sumsq[tid], s_sq[tid]);
    }
}

// ---------------- K8: BN (inline finalize) + relu + 128->2 GEMV -------------
__global__ __launch_bounds__(256) void k_node2(const float* __restrict__ W2,
                                               const float* __restrict__ gamma,
                                               const float* __restrict__ beta) {
    int n = (blockIdx.x * blockDim.x + threadIdx.x) >> 5;
    int lane = threadIdx.x & 31;
    if (n >= N_NODES) return;
    const float inv_n = 1.0f / (float)N_NODES;
    uint2 u = ((const uint2*)(g_hpre + (size_t)n * HID))[lane];
    float2 fa = __half22float2(*(__half2*)&u.x);
    float2 fb = __half22float2(*(__half2*)&u.y);
    float vv[4] = {fa.x, fa.y, fb.x, fb.y};
    float o0 = 0.f, o1 = 0.f;
    #pragma unroll
    for (int q = 0; q < 4; ++q) {
        int j = lane * 4 + q;
        float mu  = __ldg(g_sums + j) * inv_n;
        float var = __ldg(g_sumsq + j) * inv_n - mu * mu;
        float inv = rsqrtf(var + BN_EPS);
        float sc = __ldg(gamma + j) * inv;
        float sh = __ldg(beta + j) - mu * sc;
        float h = fmaf(vv[q], sc, sh);
        h = fmaxf(h, 0.f);
        o0 = fmaf(h, __ldg(W2 + j * 2 + 0), o0);
        o1 = fmaf(h, __ldg(W2 + j * 2 + 1), o1);
    }
    #pragma unroll
    for (int off = 16; off > 0; off >>= 1) {
        o0 += __shfl_xor_sync(0xffffffffu, o0, off);
        o1 += __shfl_xor_sync(0xffffffffu, o1, off);
    }
    if (lane == 0) {
        float d = g_dinv[n];
        g_h2s[n * 2 + 0] = o0 * d;
        g_h2s[n * 2 + 1] = o1 * d;
    }
}

// ---------------- K9: layer-2 aggregation (gather) + bias -------------------
__global__ __launch_bounds__(256) void k_out(const float* __restrict__ b2,
                                             float* __restrict__ out) {
    int n = (blockIdx.x * blockDim.x + threadIdx.x) >> 5;
    int lane = threadIdx.x & 31;
    if (n >= N_NODES) return;
    int s = g_off[n], e = g_off[n + 1];
    float o0 = 0.f, o1 = 0.f;
    for (int i = s + lane; i < e; i += 32) {
        int r = g_csr_row[i];
        float2 v = *(const float2*)(g_h2s + (size_t)r * 2);
        o0 += v.x; o1 += v.y;
    }
    #pragma unroll
    for (int off = 16; off > 0; off >>= 1) {
        o0 += __shfl_xor_sync(0xffffffffu, o0, off);
        o1 += __shfl_xor_sync(0xffffffffu, o1, off);
    }
    if (lane == 0) {
        float d = g_dinv[n];
        float2 self = *(const float2*)(g_h2s + (size_t)n * 2);
        out[n * 2 + 0] = d * (o0 + self.x) + __ldg(b2 + 0);
        out[n * 2 + 1] = d * (o1 + self.y) + __ldg(b2 + 1);
    }
}

// ---------------- launch ----------------------------------------------------
extern "C" void kernel_launch(void* const* d_in, const int* in_sizes, int n_in,
                              void* d_out, int out_size) {
    const float* x  = (const float*)d_in[0];
    const int*   ei = (const int*)d_in[1];
    const float* fi = (const float*)d_in[2];
    const float* W1 = (const float*)d_in[3];
    const float* b1 = (const float*)d_in[4];
    const float* W2 = (const float*)d_in[5];
    const float* b2 = (const float*)d_in[6];
    const float* gm = (const float*)d_in[7];
    const float* bt = (const float*)d_in[8];
    float* out = (float*)d_out;

    k_prep<<<(N_NODES + 255) / 256, 256>>>(W1, fi);                        // 0
    k_fuse1<<<FUSE1_BLOCKS, 256>>>(x, ei);                                 // 1 gemmA+deg interleaved
    k_scan1<<<SC_BLOCKS, SC_THREADS>>>();                                  // 2
    k_scan3<<<SC_BLOCKS, SC_THREADS>>>();                                  // 3 (ncu slot)
    k_fuse2<<<FUSE2_BLOCKS, 256>>>(x, ei);                                 // 4 gemmB+fill interleaved
    k_agg1<<<(N_NODES + 7) / 8, 256>>>(b1);                                // 5
    {
        long long tot = (long long)N_NODES * 32;
        k_node2<<<(unsigned)((tot + 255) / 256), 256>>>(W2, gm, bt);       // 6
        k_out<<<(unsigned)((tot + 255) / 256), 256>>>(b2, out);            // 7
    }
}

// round 11
// speedup vs baseline: 1.0214x; 1.0214x over previous
#include <cuda_runtime.h>
#include <cuda_fp16.h>
#include <cstdint>
#include <cstddef>

#define N_NODES 100000
#define N_EDGES 3200000
#define IN_DIM  256
#define HID     128
#define OUT_DIM 2
#define BN_EPS  1e-5f

#define SC_BLOCKS 100
#define SC_THREADS 256
#define SC_PER 4   // 100*256*4 = 102400 >= N_NODES

#define GBM 128
#define GBK 32
#define A_S 36
#define B_S 132
#define NBLK_GEMM ((N_NODES + GBM - 1) / GBM)          // 782
#define GEMM_SPLIT 370                                  // tiles fused with deg
#define NBLK_EDGE ((N_EDGES / 8 + 255) / 256)          // 1563 (deg & fill)

// ---------------- scratch (static device globals; no runtime alloc) --------
__device__ __align__(16) float  g_dinv[N_NODES];
__device__ __align__(16) __half g_h1s[(size_t)N_NODES * HID];   // fp16 h1 (unscaled)
__device__ __align__(16) __half g_hpre[(size_t)N_NODES * HID];  // fp16 pre-BN h
__device__ __align__(16) float  g_h2s[N_NODES * OUT_DIM];
__device__ __align__(16) float  g_W1s[IN_DIM * HID];            // tf32-rounded W1*sig(fi)
__device__ __align__(16) float  g_sums[HID];
__device__ __align__(16) float  g_sumsq[HID];
// CSR by destination
__device__ __align__(16) int    g_cnt[N_NODES];
__device__ __align__(16) int    g_off[N_NODES + 1];
__device__ __align__(16) int    g_cursor[N_NODES];
__device__ __align__(16) int    g_csr_row[N_EDGES];
// fused-scan scratch
__device__ __align__(16) int    g_bpart[SC_BLOCKS];
__device__ int                  g_arrive;

// ---------------- helpers ---------------------------------------------------
__device__ __forceinline__ float to_tf32(float x) {
    uint32_t u;
    asm("cvt.rna.tf32.f32 %0, %1;" : "=r"(u) : "f"(x));
    return __uint_as_float(u);
}

__device__ __forceinline__ void mma_tf32(float* c,
                                         uint32_t a0, uint32_t a1, uint32_t a2, uint32_t a3,
                                         uint32_t b0, uint32_t b1) {
    asm volatile(
        "mma.sync.aligned.m16n8k8.row.col.f32.tf32.tf32.f32 "
        "{%0,%1,%2,%3}, {%4,%5,%6,%7}, {%8,%9}, {%0,%1,%2,%3};"
        : "+f"(c[0]), "+f"(c[1]), "+f"(c[2]), "+f"(c[3])
        : "r"(a0), "r"(a1), "r"(a2), "r"(a3), "r"(b0), "r"(b1));
}

// ---------------- GEMM tile worker (one 128x128 output tile) ----------------
__device__ __forceinline__ void gemm_tile(const float* __restrict__ x, int tile) {
    __shared__ float As[GBM * A_S];
    __shared__ float Bs[GBK * B_S];
    const int m0   = tile * GBM;
    const int tid  = threadIdx.x;
    const int lane = tid & 31;
    const int wid  = tid >> 5;
    const int wm   = wid >> 2;
    const int wn   = wid & 3;
    const int grp  = lane >> 2;
    const int tg   = lane & 3;

    float acc[4][4][4];
    #pragma unroll
    for (int im = 0; im < 4; ++im)
        #pragma unroll
        for (int in = 0; in < 4; ++in)
            #pragma unroll
            for (int q = 0; q < 4; ++q) acc[im][in][q] = 0.f;

    float4 ra[4];

    auto loadA = [&](int k0) {
        #pragma unroll
        for (int p = 0; p < 4; ++p) {
            int slot = tid + p * 256;
            int r = slot >> 3;
            int q = slot & 7;
            int gm = m0 + r;
            ra[p] = make_float4(0.f, 0.f, 0.f, 0.f);
            if (gm < N_NODES)
                ra[p] = *(const float4*)(x + (size_t)gm * IN_DIM + k0 + q * 4);
        }
    };
    auto storeA = [&]() {
        #pragma unroll
        for (int p = 0; p < 4; ++p) {
            int slot = tid + p * 256;
            int r = slot >> 3;
            int q = slot & 7;
            float* dst = As + r * A_S + q * 4;
            dst[0] = to_tf32(ra[p].x);
            dst[1] = to_tf32(ra[p].y);
            dst[2] = to_tf32(ra[p].z);
            dst[3] = to_tf32(ra[p].w);
        }
    };
    auto loadstoreB = [&](int k0) {
        #pragma unroll
        for (int p = 0; p < 4; ++p) {
            int slot = tid + p * 256;
            int r = slot >> 5;
            int c = slot & 31;
            float4 v = *(const float4*)(g_W1s + (size_t)(k0 + r) * HID + c * 4);
            *(float4*)(Bs + r * B_S + c * 4) = v;   // already tf32-rounded
        }
    };

    const int NT = IN_DIM / GBK;   // 8
    loadA(0);
    for (int t = 0; t < NT; ++t) {
        storeA();
        loadstoreB(t * GBK);
        __syncthreads();
        if (t + 1 < NT) loadA((t + 1) * GBK);

        #pragma unroll
        for (int ks = 0; ks < GBK; ks += 8) {
            uint32_t a[4][4], b[4][2];
            #pragma unroll
            for (int im = 0; im < 4; ++im) {
                int mb = wm * 64 + im * 16;
                const float* pa = As + (mb + grp) * A_S + ks + tg;
                a[im][0] = __float_as_uint(pa[0]);
                a[im][1] = __float_as_uint(pa[8 * A_S]);
                a[im][2] = __float_as_uint(pa[4]);
                a[im][3] = __float_as_uint(pa[8 * A_S + 4]);
            }
            #pragma unroll
            for (int in = 0; in < 4; ++in) {
                int nb = wn * 32 + in * 8 + grp;
                const float* pb = Bs + (ks + tg) * B_S + nb;
                b[in][0] = __float_as_uint(pb[0]);
                b[in][1] = __float_as_uint(pb[4 * B_S]);
            }
            #pragma unroll
            for (int im = 0; im < 4; ++im)
                #pragma unroll
                for (int in = 0; in < 4; ++in)
                    mma_tf32(acc[im][in], a[im][0], a[im][1], a[im][2], a[im][3],
                             b[in][0], b[in][1]);
        }
        __syncthreads();
    }

    #pragma unroll
    for (int im = 0; im < 4; ++im) {
        int r0 = m0 + wm * 64 + im * 16 + grp;
        int r1 = r0 + 8;
        #pragma unroll
        for (int in = 0; in < 4; ++in) {
            int col = wn * 32 + in * 8 + tg * 2;
            if (r0 < N_NODES) {
                __half2 h = __floats2half2_rn(acc[im][in][0], acc[im][in][1]);
                *(__half2*)(g_h1s + (size_t)r0 * HID + col) = h;
            }
            if (r1 < N_NODES) {
                __half2 h = __floats2half2_rn(acc[im][in][2], acc[im][in][3]);
                *(__half2*)(g_h1s + (size_t)r1 * HID + col) = h;
            }
        }
    }
}

// ---------------- K0: prep (fold sigmoid into W1 -> tf32, zero counters) ----
__global__ void k_prep(const float* __restrict__ W1, const float* __restrict__ fi) {
    int i = blockIdx.x * blockDim.x + threadIdx.x;
    if (i < IN_DIM * HID) {
        int k = i / HID;
        float s = 1.0f / (1.0f + __expf(-fi[k]));
        g_W1s[i] = to_tf32(W1[i] * s);
    }
    if (i < N_NODES) g_cnt[i] = 0;
    if (i < HID) { g_sums[i] = 0.0f; g_sumsq[i] = 0.0f; }
    if (i == 0) g_arrive = 0;
}

// ---------------- K1: FUSED  GEMM tiles [0,SPLIT) || degree histogram -------
__global__ __launch_bounds__(256, 2) void k_fuse1(const float* __restrict__ x,
                                                  const int* __restrict__ ei) {
    if (blockIdx.x >= GEMM_SPLIT) {
        int t = (blockIdx.x - GEMM_SPLIT) * blockDim.x + threadIdx.x;
        int e8 = t * 8;
        if (e8 >= N_EDGES) return;
        int4 c0 = *(const int4*)(ei + N_EDGES + e8);
        int4 c1 = *(const int4*)(ei + N_EDGES + e8 + 4);
        atomicAdd(&g_cnt[c0.x], 1);
        atomicAdd(&g_cnt[c0.y], 1);
        atomicAdd(&g_cnt[c0.z], 1);
        atomicAdd(&g_cnt[c0.w], 1);
        atomicAdd(&g_cnt[c1.x], 1);
        atomicAdd(&g_cnt[c1.y], 1);
        atomicAdd(&g_cnt[c1.z], 1);
        atomicAdd(&g_cnt[c1.w], 1);
        return;
    }
    gemm_tile(x, blockIdx.x);
}

// ---------------- K2: FUSED scan (single kernel, device barrier) -------------
// 100 blocks (all co-resident on 148 SMs): local sums + block scan, publish
// partial, spin until all partials ready, then finalize offsets/cursor/dinv.
__global__ __launch_bounds__(SC_THREADS) void k_scanf() {
    __shared__ int sm[SC_THREADS];
    __shared__ int bp[SC_BLOCKS];
    int t = threadIdx.x, b = blockIdx.x;
    int base = (b * SC_THREADS + t) * SC_PER;
    int cnts[SC_PER];
    int s = 0;
    #pragma unroll
    for (int q = 0; q < SC_PER; ++q) {
        int i = base + q;
        cnts[q] = (i < N_NODES) ? g_cnt[i] : 0;
        s += cnts[q];
    }
    sm[t] = s;
    __syncthreads();
    for (int off = 1; off < SC_THREADS; off <<= 1) {
        int v = (t >= off) ? sm[t - off] : 0;
        __syncthreads();
        sm[t] += v;
        __syncthreads();
    }
    int tpref = sm[t] - s;   // exclusive within block
    if (t == SC_THREADS - 1) {
        g_bpart[b] = sm[t];
        __threadfence();
        atomicAdd(&g_arrive, 1);
    }
    // spin until all blocks have published their partial
    if (t == 0) {
        while (atomicAdd(&g_arrive, 0) < SC_BLOCKS) { }
    }
    __syncthreads();
    if (t < SC_BLOCKS) bp[t] = g_bpart[t];
    __syncthreads();
    if (t == 0) {
        int run = 0;
        #pragma unroll 4
        for (int i = 0; i < SC_BLOCKS; ++i) { int c = bp[i]; bp[i] = run; run += c; }
    }
    __syncthreads();
    int run = bp[b] + tpref;
    #pragma unroll
    for (int q = 0; q < SC_PER; ++q) {
        int i = base + q;
        if (i < N_NODES) {
            int c = cnts[q];
            g_off[i] = run;
            g_cursor[i] = run;
            g_dinv[i] = rsqrtf((float)(c + 1));
            run += c;
            if (i == N_NODES - 1) g_off[N_NODES] = run;
        }
    }
}

// ---------------- K3: FUSED  GEMM tiles [SPLIT,782) || CSR fill --------------
__global__ __launch_bounds__(256, 2) void k_fuse2(const float* __restrict__ x,
                                                  const int* __restrict__ ei) {
    const int NG = NBLK_GEMM - GEMM_SPLIT;
    if (blockIdx.x >= NG) {
        int t = (blockIdx.x - NG) * blockDim.x + threadIdx.x;
        int e8 = t * 8;
        if (e8 >= N_EDGES) return;
        int4 r0 = *(const int4*)(ei + e8);
        int4 r1 = *(const int4*)(ei + e8 + 4);
        int4 c0 = *(const int4*)(ei + N_EDGES + e8);
        int4 c1 = *(const int4*)(ei + N_EDGES + e8 + 4);
        int p0 = atomicAdd(&g_cursor[c0.x], 1);
        int p1 = atomicAdd(&g_cursor[c0.y], 1);
        int p2 = atomicAdd(&g_cursor[c0.z], 1);
        int p3 = atomicAdd(&g_cursor[c0.w], 1);
        int p4 = atomicAdd(&g_cursor[c1.x], 1);
        int p5 = atomicAdd(&g_cursor[c1.y], 1);
        int p6 = atomicAdd(&g_cursor[c1.z], 1);
        int p7 = atomicAdd(&g_cursor[c1.w], 1);
        g_csr_row[p0] = r0.x;
        g_csr_row[p1] = r0.y;
        g_csr_row[p2] = r0.z;
        g_csr_row[p3] = r0.w;
        g_csr_row[p4] = r1.x;
        g_csr_row[p5] = r1.y;
        g_csr_row[p6] = r1.z;
        g_csr_row[p7] = r1.w;
        return;
    }
    gemm_tile(x, GEMM_SPLIT + blockIdx.x);
}

// ---------------- K5: layer-1 aggregation (dinv at gather) + BN stats -------
__global__ __launch_bounds__(256) void k_agg1(const float* __restrict__ b1) {
    __shared__ float s_sum[HID];
    __shared__ float s_sq[HID];
    const int tid  = threadIdx.x;
    const int lane = tid & 31;
    const int warp = tid >> 5;
    if (tid < HID) { s_sum[tid] = 0.f; s_sq[tid] = 0.f; }
    __syncthreads();

    int n = blockIdx.x * 8 + warp;
    if (n < N_NODES) {
        int s = g_off[n], e = g_off[n + 1];
        float dn = g_dinv[n];
        float4 v;
        {
            uint2 u = ((const uint2*)(g_h1s + (size_t)n * HID))[lane];
            float2 fa = __half22float2(*(__half2*)&u.x);
            float2 fb = __half22float2(*(__half2*)&u.y);
            v = make_float4(dn * fa.x, dn * fa.y, dn * fb.x, dn * fb.y);
        }
        int i = s;
        for (; i + 4 <= e; i += 4) {
            int r0 = g_csr_row[i];
            int r1 = g_csr_row[i + 1];
            int r2 = g_csr_row[i + 2];
            int r3 = g_csr_row[i + 3];
            float d0 = g_dinv[r0], d1 = g_dinv[r1], d2 = g_dinv[r2], d3 = g_dinv[r3];
            uint2 u0 = ((const uint2*)(g_h1s + (size_t)r0 * HID))[lane];
            uint2 u1 = ((const uint2*)(g_h1s + (size_t)r1 * HID))[lane];
            uint2 u2 = ((const uint2*)(g_h1s + (size_t)r2 * HID))[lane];
            uint2 u3 = ((const uint2*)(g_h1s + (size_t)r3 * HID))[lane];
            float2 a0 = __half22float2(*(__half2*)&u0.x), b0 = __half22float2(*(__half2*)&u0.y);
            float2 a1 = __half22float2(*(__half2*)&u1.x), b1f = __half22float2(*(__half2*)&u1.y);
            float2 a2 = __half22float2(*(__half2*)&u2.x), b2f = __half22float2(*(__half2*)&u2.y);
            float2 a3 = __half22float2(*(__half2*)&u3.x), b3f = __half22float2(*(__half2*)&u3.y);
            v.x = fmaf(d0, a0.x, v.x); v.y = fmaf(d0, a0.y, v.y);
            v.z = fmaf(d0, b0.x, v.z); v.w = fmaf(d0, b0.y, v.w);
            v.x = fmaf(d1, a1.x, v.x); v.y = fmaf(d1, a1.y, v.y);
            v.z = fmaf(d1, b1f.x, v.z); v.w = fmaf(d1, b1f.y, v.w);
            v.x = fmaf(d2, a2.x, v.x); v.y = fmaf(d2, a2.y, v.y);
            v.z = fmaf(d2, b2f.x, v.z); v.w = fmaf(d2, b2f.y, v.w);
            v.x = fmaf(d3, a3.x, v.x); v.y = fmaf(d3, a3.y, v.y);
            v.z = fmaf(d3, b3f.x, v.z); v.w = fmaf(d3, b3f.y, v.w);
        }
        for (; i < e; ++i) {
            int r0 = g_csr_row[i];
            float d0 = g_dinv[r0];
            uint2 u0 = ((const uint2*)(g_h1s + (size_t)r0 * HID))[lane];
            float2 a0 = __half22float2(*(__half2*)&u0.x), b0 = __half22float2(*(__half2*)&u0.y);
            v.x = fmaf(d0, a0.x, v.x); v.y = fmaf(d0, a0.y, v.y);
            v.z = fmaf(d0, b0.x, v.z); v.w = fmaf(d0, b0.y, v.w);
        }

        float vv[4] = {v.x, v.y, v.z, v.w};
        float hh[4];
        #pragma unroll
        for (int q = 0; q < 4; ++q) {
            int j = lane * 4 + q;
            hh[q] = fmaf(dn, vv[q], __ldg(b1 + j));
            atomicAdd(&s_sum[j], hh[q]);
            atomicAdd(&s_sq[j], hh[q] * hh[q]);
        }
        uint2 o;
        *(__half2*)&o.x = __floats2half2_rn(hh[0], hh[1]);
        *(__half2*)&o.y = __floats2half2_rn(hh[2], hh[3]);
        ((uint2*)(g_hpre + (size_t)n * HID))[lane] = o;
    }
    __syncthreads();
    if (tid < HID) {
        atomicAdd(&g_sums[tid], s_sum[tid]);
        atomicAdd(&g_sumsq[tid], s_sq[tid]);
    }
}

// ---------------- K8: BN (inline finalize) + relu + 128->2 GEMV -------------
__global__ __launch_bounds__(256) void k_node2(const float* __restrict__ W2,
                                               const float* __restrict__ gamma,
                                               const float* __restrict__ beta) {
    int n = (blockIdx.x * blockDim.x + threadIdx.x) >> 5;
    int lane = threadIdx.x & 31;
    if (n >= N_NODES) return;
    const float inv_n = 1.0f / (float)N_NODES;
    uint2 u = ((const uint2*)(g_hpre + (size_t)n * HID))[lane];
    float2 fa = __half22float2(*(__half2*)&u.x);
    float2 fb = __half22float2(*(__half2*)&u.y);
    float vv[4] = {fa.x, fa.y, fb.x, fb.y};
    float o0 = 0.f, o1 = 0.f;
    #pragma unroll
    for (int q = 0; q < 4; ++q) {
        int j = lane * 4 + q;
        float mu  = __ldg(g_sums + j) * inv_n;
        float var = __ldg(g_sumsq + j) * inv_n - mu * mu;
        float inv = rsqrtf(var + BN_EPS);
        float sc = __ldg(gamma + j) * inv;
        float sh = __ldg(beta + j) - mu * sc;
        float h = fmaf(vv[q], sc, sh);
        h = fmaxf(h, 0.f);
        o0 = fmaf(h, __ldg(W2 + j * 2 + 0), o0);
        o1 = fmaf(h, __ldg(W2 + j * 2 + 1), o1);
    }
    #pragma unroll
    for (int off = 16; off > 0; off >>= 1) {
        o0 += __shfl_xor_sync(0xffffffffu, o0, off);
        o1 += __shfl_xor_sync(0xffffffffu, o1, off);
    }
    if (lane == 0) {
        float d = g_dinv[n];
        g_h2s[n * 2 + 0] = o0 * d;
        g_h2s[n * 2 + 1] = o1 * d;
    }
}

// ---------------- K9: layer-2 aggregation (gather) + bias -------------------
__global__ __launch_bounds__(256) void k_out(const float* __restrict__ b2,
                                             float* __restrict__ out) {
    int n = (blockIdx.x * blockDim.x + threadIdx.x) >> 5;
    int lane = threadIdx.x & 31;
    if (n >= N_NODES) return;
    int s = g_off[n], e = g_off[n + 1];
    float o0 = 0.f, o1 = 0.f;
    for (int i = s + lane; i < e; i += 32) {
        int r = __ldg(g_csr_row + i);
        float2 v = *(const float2*)(g_h2s + (size_t)r * 2);
        o0 += v.x; o1 += v.y;
    }
    #pragma unroll
    for (int off = 16; off > 0; off >>= 1) {
        o0 += __shfl_xor_sync(0xffffffffu, o0, off);
        o1 += __shfl_xor_sync(0xffffffffu, o1, off);
    }
    if (lane == 0) {
        float d = g_dinv[n];
        float2 self = *(const float2*)(g_h2s + (size_t)n * 2);
        out[n * 2 + 0] = d * (o0 + self.x) + __ldg(b2 + 0);
        out[n * 2 + 1] = d * (o1 + self.y) + __ldg(b2 + 1);
    }
}

// ---------------- launch ----------------------------------------------------
extern "C" void kernel_launch(void* const* d_in, const int* in_sizes, int n_in,
                              void* d_out, int out_size) {
    const float* x  = (const float*)d_in[0];
    const int*   ei = (const int*)d_in[1];
    const float* fi = (const float*)d_in[2];
    const float* W1 = (const float*)d_in[3];
    const float* b1 = (const float*)d_in[4];
    const float* W2 = (const float*)d_in[5];
    const float* b2 = (const float*)d_in[6];
    const float* gm = (const float*)d_in[7];
    const float* bt = (const float*)d_in[8];
    float* out = (float*)d_out;

    k_prep<<<(N_NODES + 255) / 256, 256>>>(W1, fi);                        // 0
    k_fuse1<<<GEMM_SPLIT + NBLK_EDGE, 256>>>(x, ei);                       // 1 gemmA||deg
    k_scanf<<<SC_BLOCKS, SC_THREADS>>>();                                  // 2 fused scan
    k_fuse2<<<(NBLK_GEMM - GEMM_SPLIT) + NBLK_EDGE, 256>>>(x, ei);         // 3 gemmB||fill (ncu)
    k_agg1<<<(N_NODES + 7) / 8, 256>>>(b1);                                // 4
    {
        long long tot = (long long)N_NODES * 32;
        k_node2<<<(unsigned)((tot + 255) / 256), 256>>>(W2, gm, bt);       // 5
        k_out<<<(unsigned)((tot + 255) / 256), 256>>>(b2, out);            // 6
    }
}

// round 12
// speedup vs baseline: 1.0279x; 1.0064x over previous
#include <cuda_runtime.h>
#include <cuda_fp16.h>
#include <cstdint>
#include <cstddef>

#define N_NODES 100000
#define N_EDGES 3200000
#define IN_DIM  256
#define HID     128
#define OUT_DIM 2
#define BN_EPS  1e-5f

#define SC_BLOCKS 100
#define SC_THREADS 256
#define SC_PER 4   // 100*256*4 = 102400 >= N_NODES

#define GBM 128
#define GBK 32
#define A_S 36
#define B_S 132
#define NBLK_GEMM ((N_NODES + GBM - 1) / GBM)          // 782
#define NBLK_EDGE ((N_EDGES / 8 + 255) / 256)          // 1563

// ---------------- scratch (static device globals; no runtime alloc) --------
__device__ __align__(16) float  g_dinv[N_NODES];
__device__ __align__(16) __half g_h1s[(size_t)N_NODES * HID];   // fp16 h1 (unscaled)
__device__ __align__(16) __half g_hpre[(size_t)N_NODES * HID];  // fp16 pre-BN h
__device__ __align__(16) float  g_h2s[N_NODES * OUT_DIM];
__device__ __align__(16) float  g_W1s[IN_DIM * HID];            // tf32-rounded W1*sig(fi)
__device__ __align__(16) float  g_sums[HID];
__device__ __align__(16) float  g_sumsq[HID];
// CSR by destination
__device__ __align__(16) int    g_cnt[N_NODES];
__device__ __align__(16) int    g_off[N_NODES + 1];
__device__ __align__(16) int    g_cursor[N_NODES];
__device__ __align__(16) int    g_csr_row[N_EDGES];
// fused-scan scratch
__device__ __align__(16) int    g_bpart[SC_BLOCKS];
__device__ int                  g_arrive;

// ---------------- helpers ---------------------------------------------------
__device__ __forceinline__ float to_tf32(float x) {
    uint32_t u;
    asm("cvt.rna.tf32.f32 %0, %1;" : "=r"(u) : "f"(x));
    return __uint_as_float(u);
}

__device__ __forceinline__ void mma_tf32(float* c,
                                         uint32_t a0, uint32_t a1, uint32_t a2, uint32_t a3,
                                         uint32_t b0, uint32_t b1) {
    asm volatile(
        "mma.sync.aligned.m16n8k8.row.col.f32.tf32.tf32.f32 "
        "{%0,%1,%2,%3}, {%4,%5,%6,%7}, {%8,%9}, {%0,%1,%2,%3};"
        : "+f"(c[0]), "+f"(c[1]), "+f"(c[2]), "+f"(c[3])
        : "r"(a0), "r"(a1), "r"(a2), "r"(a3), "r"(b0), "r"(b1));
}

// ---------------- K0: prep (fold sigmoid into W1 -> tf32, zero counters) ----
__global__ void k_prep(const float* __restrict__ W1, const float* __restrict__ fi) {
    int i = blockIdx.x * blockDim.x + threadIdx.x;
    if (i < IN_DIM * HID) {
        int k = i / HID;
        float s = 1.0f / (1.0f + __expf(-fi[k]));
        g_W1s[i] = to_tf32(W1[i] * s);
    }
    if (i < N_NODES) g_cnt[i] = 0;
    if (i < HID) { g_sums[i] = 0.0f; g_sumsq[i] = 0.0f; }
    if (i == 0) g_arrive = 0;
}

// ---------------- K_GEMM: standalone tf32 GEMM (side stream) ----------------
__global__ __launch_bounds__(256, 2) void k_gemm1(const float* __restrict__ x) {
    __shared__ float As[GBM * A_S];
    __shared__ float Bs[GBK * B_S];
    const int m0   = blockIdx.x * GBM;
    const int tid  = threadIdx.x;
    const int lane = tid & 31;
    const int wid  = tid >> 5;
    const int wm   = wid >> 2;
    const int wn   = wid & 3;
    const int grp  = lane >> 2;
    const int tg   = lane & 3;

    float acc[4][4][4];
    #pragma unroll
    for (int im = 0; im < 4; ++im)
        #pragma unroll
        for (int in = 0; in < 4; ++in)
            #pragma unroll
            for (int q = 0; q < 4; ++q) acc[im][in][q] = 0.f;

    float4 ra[4];

    auto loadA = [&](int k0) {
        #pragma unroll
        for (int p = 0; p < 4; ++p) {
            int slot = tid + p * 256;
            int r = slot >> 3;
            int q = slot & 7;
            int gm = m0 + r;
            ra[p] = make_float4(0.f, 0.f, 0.f, 0.f);
            if (gm < N_NODES)
                ra[p] = *(const float4*)(x + (size_t)gm * IN_DIM + k0 + q * 4);
        }
    };
    auto storeA = [&]() {
        #pragma unroll
        for (int p = 0; p < 4; ++p) {
            int slot = tid + p * 256;
            int r = slot >> 3;
            int q = slot & 7;
            float* dst = As + r * A_S + q * 4;
            dst[0] = to_tf32(ra[p].x);
            dst[1] = to_tf32(ra[p].y);
            dst[2] = to_tf32(ra[p].z);
            dst[3] = to_tf32(ra[p].w);
        }
    };
    auto loadstoreB = [&](int k0) {
        #pragma unroll
        for (int p = 0; p < 4; ++p) {
            int slot = tid + p * 256;
            int r = slot >> 5;
            int c = slot & 31;
            float4 v = *(const float4*)(g_W1s + (size_t)(k0 + r) * HID + c * 4);
            *(float4*)(Bs + r * B_S + c * 4) = v;   // already tf32-rounded
        }
    };

    const int NT = IN_DIM / GBK;   // 8
    loadA(0);
    for (int t = 0; t < NT; ++t) {
        storeA();
        loadstoreB(t * GBK);
        __syncthreads();
        if (t + 1 < NT) loadA((t + 1) * GBK);

        #pragma unroll
        for (int ks = 0; ks < GBK; ks += 8) {
            uint32_t a[4][4], b[4][2];
            #pragma unroll
            for (int im = 0; im < 4; ++im) {
                int mb = wm * 64 + im * 16;
                const float* pa = As + (mb + grp) * A_S + ks + tg;
                a[im][0] = __float_as_uint(pa[0]);
                a[im][1] = __float_as_uint(pa[8 * A_S]);
                a[im][2] = __float_as_uint(pa[4]);
                a[im][3] = __float_as_uint(pa[8 * A_S + 4]);
            }
            #pragma unroll
            for (int in = 0; in < 4; ++in) {
                int nb = wn * 32 + in * 8 + grp;
                const float* pb = Bs + (ks + tg) * B_S + nb;
                b[in][0] = __float_as_uint(pb[0]);
                b[in][1] = __float_as_uint(pb[4 * B_S]);
            }
            #pragma unroll
            for (int im = 0; im < 4; ++im)
                #pragma unroll
                for (int in = 0; in < 4; ++in)
                    mma_tf32(acc[im][in], a[im][0], a[im][1], a[im][2], a[im][3],
                             b[in][0], b[in][1]);
        }
        __syncthreads();
    }

    #pragma unroll
    for (int im = 0; im < 4; ++im) {
        int r0 = m0 + wm * 64 + im * 16 + grp;
        int r1 = r0 + 8;
        #pragma unroll
        for (int in = 0; in < 4; ++in) {
            int col = wn * 32 + in * 8 + tg * 2;
            if (r0 < N_NODES) {
                __half2 h = __floats2half2_rn(acc[im][in][0], acc[im][in][1]);
                *(__half2*)(g_h1s + (size_t)r0 * HID + col) = h;
            }
            if (r1 < N_NODES) {
                __half2 h = __floats2half2_rn(acc[im][in][2], acc[im][in][3]);
                *(__half2*)(g_h1s + (size_t)r1 * HID + col) = h;
            }
        }
    }
}

// ---------------- K1: in-degree histogram (standalone, high occupancy) ------
__global__ void k_deg(const int* __restrict__ ei) {
    int t = blockIdx.x * blockDim.x + threadIdx.x;
    int e8 = t * 8;
    if (e8 >= N_EDGES) return;
    int4 c0 = *(const int4*)(ei + N_EDGES + e8);
    int4 c1 = *(const int4*)(ei + N_EDGES + e8 + 4);
    atomicAdd(&g_cnt[c0.x], 1);
    atomicAdd(&g_cnt[c0.y], 1);
    atomicAdd(&g_cnt[c0.z], 1);
    atomicAdd(&g_cnt[c0.w], 1);
    atomicAdd(&g_cnt[c1.x], 1);
    atomicAdd(&g_cnt[c1.y], 1);
    atomicAdd(&g_cnt[c1.z], 1);
    atomicAdd(&g_cnt[c1.w], 1);
}

// ---------------- K2: FUSED scan (single kernel, device barrier) -------------
__global__ __launch_bounds__(SC_THREADS) void k_scanf() {
    __shared__ int sm[SC_THREADS];
    __shared__ int bp[SC_BLOCKS];
    int t = threadIdx.x, b = blockIdx.x;
    int base = (b * SC_THREADS + t) * SC_PER;
    int cnts[SC_PER];
    int s = 0;
    #pragma unroll
    for (int q = 0; q < SC_PER; ++q) {
        int i = base + q;
        cnts[q] = (i < N_NODES) ? g_cnt[i] : 0;
        s += cnts[q];
    }
    sm[t] = s;
    __syncthreads();
    for (int off = 1; off < SC_THREADS; off <<= 1) {
        int v = (t >= off) ? sm[t - off] : 0;
        __syncthreads();
        sm[t] += v;
        __syncthreads();
    }
    int tpref = sm[t] - s;   // exclusive within block
    if (t == SC_THREADS - 1) {
        g_bpart[b] = sm[t];
        __threadfence();
        atomicAdd(&g_arrive, 1);
    }
    if (t == 0) {
        while (atomicAdd(&g_arrive, 0) < SC_BLOCKS) { }
    }
    __syncthreads();
    if (t < SC_BLOCKS) bp[t] = g_bpart[t];
    __syncthreads();
    if (t == 0) {
        int run = 0;
        #pragma unroll 4
        for (int i = 0; i < SC_BLOCKS; ++i) { int c = bp[i]; bp[i] = run; run += c; }
    }
    __syncthreads();
    int run = bp[b] + tpref;
    #pragma unroll
    for (int q = 0; q < SC_PER; ++q) {
        int i = base + q;
        if (i < N_NODES) {
            int c = cnts[q];
            g_off[i] = run;
            g_cursor[i] = run;
            g_dinv[i] = rsqrtf((float)(c + 1));
            run += c;
            if (i == N_NODES - 1) g_off[N_NODES] = run;
        }
    }
}

// ---------------- K3: fill CSR source indices (standalone) ------------------
__global__ void k_fill(const int* __restrict__ ei) {
    int t = blockIdx.x * blockDim.x + threadIdx.x;
    int e8 = t * 8;
    if (e8 >= N_EDGES) return;
    int4 r0 = *(const int4*)(ei + e8);
    int4 r1 = *(const int4*)(ei + e8 + 4);
    int4 c0 = *(const int4*)(ei + N_EDGES + e8);
    int4 c1 = *(const int4*)(ei + N_EDGES + e8 + 4);
    int p0 = atomicAdd(&g_cursor[c0.x], 1);
    int p1 = atomicAdd(&g_cursor[c0.y], 1);
    int p2 = atomicAdd(&g_cursor[c0.z], 1);
    int p3 = atomicAdd(&g_cursor[c0.w], 1);
    int p4 = atomicAdd(&g_cursor[c1.x], 1);
    int p5 = atomicAdd(&g_cursor[c1.y], 1);
    int p6 = atomicAdd(&g_cursor[c1.z], 1);
    int p7 = atomicAdd(&g_cursor[c1.w], 1);
    g_csr_row[p0] = r0.x;
    g_csr_row[p1] = r0.y;
    g_csr_row[p2] = r0.z;
    g_csr_row[p3] = r0.w;
    g_csr_row[p4] = r1.x;
    g_csr_row[p5] = r1.y;
    g_csr_row[p6] = r1.z;
    g_csr_row[p7] = r1.w;
}

// ---------------- K5: layer-1 aggregation (dinv at gather) + BN stats -------
__global__ __launch_bounds__(256) void k_agg1(const float* __restrict__ b1) {
    __shared__ float s_sum[HID];
    __shared__ float s_sq[HID];
    const int tid  = threadIdx.x;
    const int lane = tid & 31;
    const int warp = tid >> 5;
    if (tid < HID) { s_sum[tid] = 0.f; s_sq[tid] = 0.f; }
    __syncthreads();

    int n = blockIdx.x * 8 + warp;
    if (n < N_NODES) {
        int s = g_off[n], e = g_off[n + 1];
        float dn = g_dinv[n];
        float4 v;
        {
            uint2 u = ((const uint2*)(g_h1s + (size_t)n * HID))[lane];
            float2 fa = __half22float2(*(__half2*)&u.x);
            float2 fb = __half22float2(*(__half2*)&u.y);
            v = make_float4(dn * fa.x, dn * fa.y, dn * fb.x, dn * fb.y);
        }
        int i = s;
        for (; i + 4 <= e; i += 4) {
            int r0 = g_csr_row[i];
            int r1 = g_csr_row[i + 1];
            int r2 = g_csr_row[i + 2];
            int r3 = g_csr_row[i + 3];
            float d0 = g_dinv[r0], d1 = g_dinv[r1], d2 = g_dinv[r2], d3 = g_dinv[r3];
            uint2 u0 = ((const uint2*)(g_h1s + (size_t)r0 * HID))[lane];
            uint2 u1 = ((const uint2*)(g_h1s + (size_t)r1 * HID))[lane];
            uint2 u2 = ((const uint2*)(g_h1s + (size_t)r2 * HID))[lane];
            uint2 u3 = ((const uint2*)(g_h1s + (size_t)r3 * HID))[lane];
            float2 a0 = __half22float2(*(__half2*)&u0.x), b0 = __half22float2(*(__half2*)&u0.y);
            float2 a1 = __half22float2(*(__half2*)&u1.x), b1f = __half22float2(*(__half2*)&u1.y);
            float2 a2 = __half22float2(*(__half2*)&u2.x), b2f = __half22float2(*(__half2*)&u2.y);
            float2 a3 = __half22float2(*(__half2*)&u3.x), b3f = __half22float2(*(__half2*)&u3.y);
            v.x = fmaf(d0, a0.x, v.x); v.y = fmaf(d0, a0.y, v.y);
            v.z = fmaf(d0, b0.x, v.z); v.w = fmaf(d0, b0.y, v.w);
            v.x = fmaf(d1, a1.x, v.x); v.y = fmaf(d1, a1.y, v.y);
            v.z = fmaf(d1, b1f.x, v.z); v.w = fmaf(d1, b1f.y, v.w);
            v.x = fmaf(d2, a2.x, v.x); v.y = fmaf(d2, a2.y, v.y);
            v.z = fmaf(d2, b2f.x, v.z); v.w = fmaf(d2, b2f.y, v.w);
            v.x = fmaf(d3, a3.x, v.x); v.y = fmaf(d3, a3.y, v.y);
            v.z = fmaf(d3, b3f.x, v.z); v.w = fmaf(d3, b3f.y, v.w);
        }
        for (; i < e; ++i) {
            int r0 = g_csr_row[i];
            float d0 = g_dinv[r0];
            uint2 u0 = ((const uint2*)(g_h1s + (size_t)r0 * HID))[lane];
            float2 a0 = __half22float2(*(__half2*)&u0.x), b0 = __half22float2(*(__half2*)&u0.y);
            v.x = fmaf(d0, a0.x, v.x); v.y = fmaf(d0, a0.y, v.y);
            v.z = fmaf(d0, b0.x, v.z); v.w = fmaf(d0, b0.y, v.w);
        }

        float vv[4] = {v.x, v.y, v.z, v.w};
        float hh[4];
        #pragma unroll
        for (int q = 0; q < 4; ++q) {
            int j = lane * 4 + q;
            hh[q] = fmaf(dn, vv[q], __ldg(b1 + j));
            atomicAdd(&s_sum[j], hh[q]);
            atomicAdd(&s_sq[j], hh[q] * hh[q]);
        }
        uint2 o;
        *(__half2*)&o.x = __floats2half2_rn(hh[0], hh[1]);
        *(__half2*)&o.y = __floats2half2_rn(hh[2], hh[3]);
        ((uint2*)(g_hpre + (size_t)n * HID))[lane] = o;
    }
    __syncthreads();
    if (tid < HID) {
        atomicAdd(&g_sums[tid], s_sum[tid]);
        atomicAdd(&g_sumsq[tid], s_sq[tid]);
    }
}

// ---------------- K8: BN (inline finalize) + relu + 128->2 GEMV -------------
__global__ __launch_bounds__(256) void k_node2(const float* __restrict__ W2,
                                               const float* __restrict__ gamma,
                                               const float* __restrict__ beta) {
    int n = (blockIdx.x * blockDim.x + threadIdx.x) >> 5;
    int lane = threadIdx.x & 31;
    if (n >= N_NODES) return;
    const float inv_n = 1.0f / (float)N_NODES;
    uint2 u = ((const uint2*)(g_hpre + (size_t)n * HID))[lane];
    float2 fa = __half22float2(*(__half2*)&u.x);
    float2 fb = __half22float2(*(__half2*)&u.y);
    float vv[4] = {fa.x, fa.y, fb.x, fb.y};
    float o0 = 0.f, o1 = 0.f;
    #pragma unroll
    for (int q = 0; q < 4; ++q) {
        int j = lane * 4 + q;
        float mu  = __ldg(g_sums + j) * inv_n;
        float var = __ldg(g_sumsq + j) * inv_n - mu * mu;
        float inv = rsqrtf(var + BN_EPS);
        float sc = __ldg(gamma + j) * inv;
        float sh = __ldg(beta + j) - mu * sc;
        float h = fmaf(vv[q], sc, sh);
        h = fmaxf(h, 0.f);
        o0 = fmaf(h, __ldg(W2 + j * 2 + 0), o0);
        o1 = fmaf(h, __ldg(W2 + j * 2 + 1), o1);
    }
    #pragma unroll
    for (int off = 16; off > 0; off >>= 1) {
        o0 += __shfl_xor_sync(0xffffffffu, o0, off);
        o1 += __shfl_xor_sync(0xffffffffu, o1, off);
    }
    if (lane == 0) {
        float d = g_dinv[n];
        g_h2s[n * 2 + 0] = o0 * d;
        g_h2s[n * 2 + 1] = o1 * d;
    }
}

// ---------------- K9: layer-2 aggregation (gather) + bias -------------------
__global__ __launch_bounds__(256) void k_out(const float* __restrict__ b2,
                                             float* __restrict__ out) {
    int n = (blockIdx.x * blockDim.x + threadIdx.x) >> 5;
    int lane = threadIdx.x & 31;
    if (n >= N_NODES) return;
    int s = g_off[n], e = g_off[n + 1];
    float o0 = 0.f, o1 = 0.f;
    for (int i = s + lane; i < e; i += 32) {
        int r = __ldg(g_csr_row + i);
        float2 v = *(const float2*)(g_h2s + (size_t)r * 2);
        o0 += v.x; o1 += v.y;
    }
    #pragma unroll
    for (int off = 16; off > 0; off >>= 1) {
        o0 += __shfl_xor_sync(0xffffffffu, o0, off);
        o1 += __shfl_xor_sync(0xffffffffu, o1, off);
    }
    if (lane == 0) {
        float d = g_dinv[n];
        float2 self = *(const float2*)(g_h2s + (size_t)n * 2);
        out[n * 2 + 0] = d * (o0 + self.x) + __ldg(b2 + 0);
        out[n * 2 + 1] = d * (o1 + self.y) + __ldg(b2 + 1);
    }
}

// ---------------- launch: two-stream fork-join (graph-capture branches) -----
extern "C" void kernel_launch(void* const* d_in, const int* in_sizes, int n_in,
                              void* d_out, int out_size) {
    const float* x  = (const float*)d_in[0];
    const int*   ei = (const int*)d_in[1];
    const float* fi = (const float*)d_in[2];
    const float* W1 = (const float*)d_in[3];
    const float* b1 = (const float*)d_in[4];
    const float* W2 = (const float*)d_in[5];
    const float* b2 = (const float*)d_in[6];
    const float* gm = (const float*)d_in[7];
    const float* bt = (const float*)d_in[8];
    float* out = (float*)d_out;

    // Fork a side stream for the GEMM branch. Created fresh each call
    // (deterministic, identical work every call); not destroyed because a
    // capture-participating stream/event cannot be destroyed before the
    // harness ends capture. kernel_launch runs O(1) times, so the host-side
    // leak is bounded and touches no device memory.
    cudaStream_t s2;
    cudaStreamCreateWithFlags(&s2, cudaStreamNonBlocking);
    cudaEvent_t ev_fork, ev_join;
    cudaEventCreateWithFlags(&ev_fork, cudaEventDisableTiming);
    cudaEventCreateWithFlags(&ev_join, cudaEventDisableTiming);

    // main (capture) stream = per-thread default stream
    k_prep<<<(N_NODES + 255) / 256, 256>>>(W1, fi);

    cudaEventRecord(ev_fork, cudaStreamPerThread);
    cudaStreamWaitEvent(s2, ev_fork, 0);

    // branch A (side stream): the full GEMM, its own occupancy envelope
    k_gemm1<<<NBLK_GEMM, 256, 0, s2>>>(x);

    // branch B (main stream): CSR build chain at high occupancy
    k_deg<<<NBLK_EDGE, 256>>>(ei);
    k_scanf<<<SC_BLOCKS, SC_THREADS>>>();
    k_fill<<<NBLK_EDGE, 256>>>(ei);

    // join
    cudaEventRecord(ev_join, s2);
    cudaStreamWaitEvent(cudaStreamPerThread, ev_join, 0);

    k_agg1<<<(N_NODES + 7) / 8, 256>>>(b1);
    {
        long long tot = (long long)N_NODES * 32;
        k_node2<<<(unsigned)((tot + 255) / 256), 256>>>(W2, gm, bt);
        k_out<<<(unsigned)((tot + 255) / 256), 256>>>(b2, out);
    }
}